// round 11
// baseline (speedup 1.0000x reference)
#include <cuda_runtime.h>
#include <cuda_bf16.h>
#include <cstdint>

// MaxUnpool2D with SMEM-staged TMA bulk writes.
// Each block: pooled tile (b, h, w0..w0+63, all 64 channels) -> builds its two
// output rows (ho, ho+1) x (wo span 128) x 64ch = 2 x 32KB CONTIGUOUS in SMEM,
// then drains each with one cp.async.bulk shared->global (32KB burst).
// This replaces the 4-way interleaved 512B STG streams (DRAM page thrash,
// measured plateau at ~63% DRAM) with maximal-page-locality bulk writes.
// Reads remain fully coalesced contiguous LDG (block reads a 16KB+16KB span).
// Argmax indices unique per pooled cell -> every output written exactly once.
//
// x:    [B=8, H=128, W=128, C=64] float32
// mask: [B, H, W, C] int32
// out:  [B, 256, 256, 64] float32

static constexpr int Bc   = 8;
static constexpr int Hc   = 128;
static constexpr int Wc   = 128;
static constexpr int Cc   = 64;
static constexpr int HOUT = 256;
static constexpr int WOUT = 256;
static constexpr int C4   = Cc / 4;          // 16
static constexpr int WT   = 64;              // pooled w per block
static constexpr int GPB  = WT * C4;         // 1024 float4 groups per block
static constexpr int THREADS = 256;
static constexpr int ITER = GPB / THREADS;   // 4
// SMEM: 2 output rows x 128 wo x 16 float4 = 2 x 32KB
static constexpr int ROW4 = 2 * WT * C4;     // 2048 float4 per output row span

__device__ __forceinline__ uint32_t smem_u32(const void* p) {
    uint32_t a;
    asm("{ .reg .u64 t; cvta.to.shared.u64 t, %1; cvt.u32.u64 %0, t; }"
        : "=r"(a) : "l"(p));
    return a;
}

__global__ __launch_bounds__(THREADS, 3) void max_unpool_bulk(
    const float4* __restrict__ x4,
    const int4*   __restrict__ m4,
    float*        __restrict__ out)
{
    __shared__ float4 buf[2][ROW4];          // 64 KB

    int bx = blockIdx.x;                     // 0..2047
    int wx = bx & 1;                         // half-row select
    int h  = (bx >> 1) & (Hc - 1);
    int b  = bx >> 8;

    int w0   = wx * WT;
    int base = ((b * Hc + h) * Wc + w0) * C4;   // first pooled group of block
    int ho   = h << 1;

    int tid = threadIdx.x;

    // Preload all iterations' data (8 independent loads in flight).
    int4   m[ITER];
    float4 v[ITER];
#pragma unroll
    for (int i = 0; i < ITER; ++i) {
        int g = base + tid + i * THREADS;
        m[i] = __ldcs(&m4[g]);
        v[i] = __ldcs(&x4[g]);
    }

#pragma unroll
    for (int i = 0; i < ITER; ++i) {
        int l  = tid + i * THREADS;          // local group
        int wl = l >> 4;                     // 0..63
        int c4 = l & (C4 - 1);
        int c  = c4 << 2;
        int wo = (w0 + wl) << 1;

#pragma unroll
        for (int dh = 0; dh < 2; ++dh) {
#pragma unroll
            for (int dw = 0; dw < 2; ++dw) {
                int flat = (((ho + dh) * WOUT) + (wo + dw)) * Cc + c;
                float4 o;
                o.x = (m[i].x == flat    ) ? v[i].x : 0.0f;
                o.y = (m[i].y == flat + 1) ? v[i].y : 0.0f;
                o.z = (m[i].z == flat + 2) ? v[i].z : 0.0f;
                o.w = (m[i].w == flat + 3) ? v[i].w : 0.0f;
                buf[dh][((wl << 1) + dw) * C4 + c4] = o;
            }
        }
    }

    // Order generic-proxy SMEM writes before async-proxy bulk reads.
    asm volatile("fence.proxy.async.shared::cta;" ::: "memory");
    __syncthreads();

    // Two 32KB bulk copies: SMEM row -> contiguous GMEM output row span.
    if (tid < 2) {
        int dh = tid;
        // float offset of (b, ho+dh, 2*w0, 0)
        size_t goff = ((size_t)(b * HOUT + ho + dh) * WOUT + (w0 << 1)) * Cc;
        uint32_t saddr = smem_u32(&buf[dh][0]);
        asm volatile(
            "cp.async.bulk.global.shared::cta.bulk_group [%0], [%1], %2;"
            :: "l"(out + goff), "r"(saddr), "n"(ROW4 * 16)
            : "memory");
        asm volatile("cp.async.bulk.commit_group;" ::: "memory");
        asm volatile("cp.async.bulk.wait_group 0;" ::: "memory");
    }
    __syncthreads();   // keep SMEM alive until bulk reads complete
}

extern "C" void kernel_launch(void* const* d_in, const int* in_sizes, int n_in,
                              void* d_out, int out_size)
{
    const float4* x4 = (const float4*)d_in[0];   // input_pool float32
    const int4*   m4 = (const int4*)  d_in[1];   // pool_mask int32
    float*        o  = (float*)d_out;

    int blocks = Bc * Hc * (Wc / WT);            // 2048
    max_unpool_bulk<<<blocks, THREADS>>>(x4, m4, o);
}

// round 12
// speedup vs baseline: 1.0100x; 1.0100x over previous
#include <cuda_runtime.h>
#include <cuda_bf16.h>
#include <cstdint>

// MaxUnpool2D — final form. Scatter-shaped gather: one thread per pooled
// float4 group; 2 coalesced 16B loads + 4 coalesced 16B stores covering the
// cell's private 2x2 output window. Argmax indices are unique per pooled
// cell -> every output element written exactly once; no atomics, no zero-init.
//
// Measured across 5 structurally different designs (multi-wave STG, far-pair
// MLP=2, persistent wave, write-through, TMA 32KB bulk writes): all converge
// at kernel ~28.5-29us = 6.7 TB/s effective for the 192MB demand traffic —
// the practical DRAM ceiling for this 2:1 write:read mix. This is the
// best-measured variant with dead bounds-check removed (grid exactly covers
// N4) and __ldcs/__stwt policies (streaming read-once / write-through).
//
// x:    [B=8, H=128, W=128, C=64] float32
// mask: [B, H, W, C] int32 (flat idx into [HOUT*WOUT*C] per batch)
// out:  [B, 256, 256, C] float32

static constexpr int Bc   = 8;
static constexpr int Hc   = 128;
static constexpr int Wc   = 128;
static constexpr int Cc   = 64;
static constexpr int HOUT = 256;
static constexpr int WOUT = 256;
static constexpr int C4   = Cc / 4;             // 16
static constexpr int N4   = Bc * Hc * Wc * C4;  // 2,097,152 pooled float4 groups
static constexpr int THREADS = 256;
static constexpr int BLOCKS  = N4 / THREADS;    // 8192 — exact, no tail

__global__ __launch_bounds__(THREADS) void max_unpool_final(
    const float4* __restrict__ x4,
    const int4*   __restrict__ m4,
    float4*       __restrict__ out4)
{
    int idx = blockIdx.x * THREADS + threadIdx.x;   // always < N4 (exact grid)

    // Issue both loads immediately.
    int4   m = __ldcs(&m4[idx]);
    float4 v = __ldcs(&x4[idx]);

    // idx -> (b, h, w, c4); all pow2 dims -> shifts/masks only.
    int c4 = idx & (C4 - 1);
    int t  = idx >> 4;
    int w  = t & (Wc - 1);
    t >>= 7;
    int h  = t & (Hc - 1);
    int b  = t >> 7;

    int c  = c4 << 2;
    int ho = h << 1;
    int wo = w << 1;

    // Output float4 offset of (b, ho, wo, c4).
    int obase = ((b * HOUT + ho) * WOUT + wo) * C4 + c4;
    // Expected argmax flat index (lane .x) at (ho, wo).
    int flat0 = (ho * WOUT + wo) * Cc + c;

#pragma unroll
    for (int dh = 0; dh < 2; ++dh) {
#pragma unroll
        for (int dw = 0; dw < 2; ++dw) {
            int flat = flat0 + dh * (WOUT * Cc) + dw * Cc;
            float4 o;
            o.x = (m.x == flat    ) ? v.x : 0.0f;
            o.y = (m.y == flat + 1) ? v.y : 0.0f;
            o.z = (m.z == flat + 2) ? v.z : 0.0f;
            o.w = (m.w == flat + 3) ? v.w : 0.0f;
            __stwt(&out4[obase + dh * (WOUT * C4) + dw * C4], o);
        }
    }
}

extern "C" void kernel_launch(void* const* d_in, const int* in_sizes, int n_in,
                              void* d_out, int out_size)
{
    const float4* x4 = (const float4*)d_in[0];   // input_pool float32
    const int4*   m4 = (const int4*)  d_in[1];   // pool_mask int32
    float4*       o4 = (float4*)d_out;

    max_unpool_final<<<BLOCKS, THREADS>>>(x4, m4, o4);
}